// round 16
// baseline (speedup 1.0000x reference)
#include <cuda_runtime.h>
#include <cuda_fp16.h>
#include <cstdint>

// ---------------- problem constants ----------------
#define MAXN   50000
#define DDIM   256
#define NSTEPS 5
#define N1     1536            // g_big cols: 3*256 (t) + 768 (gh)
#define N2     768             // GEMM2 output cols (gi)

// ---------------- device-global scratch ----------------
__device__ float g_h[2][(size_t)MAXN * DDIM];        // ping-pong node state (fp32)
__device__ float g_big[(size_t)MAXN * N1];           // [t(e0)|t(e1)|t(e2)|gh] per row
__device__ float g_gi[(size_t)MAXN * N2];            // a @ w_ih^T
__device__ float g_a[(size_t)MAXN * DDIM];           // aggregated messages
__device__ float g_gate[MAXN];

__device__ __half g_hb[(size_t)MAXN * DDIM];         // h split hi (fp16)
__device__ __half g_hl[(size_t)MAXN * DDIM];         // h split lo (fp16)
__device__ __half g_ab[(size_t)MAXN * DDIM];         // a split hi
__device__ __half g_al[(size_t)MAXN * DDIM];         // a split lo
__device__ __half g_W1h[N1 * DDIM];                  // packed [n][k] weights (fp16)
__device__ __half g_W2h[N2 * DDIM];

// ---------------- small helpers ----------------
__device__ __forceinline__ float sigf(float x) { return 1.f / (1.f + __expf(-x)); }

__device__ __forceinline__ uint32_t smem_u32(const void* p) {
    uint32_t a;
    asm("{ .reg .u64 t; cvta.to.shared.u64 t, %1; cvt.u32.u64 %0, t; }"
        : "=r"(a) : "l"(p));
    return a;
}

__device__ __forceinline__ void split1(float v, __half& h, __half& l) {
    h = __float2half_rn(v);
    l = __float2half_rn(v - __half2float(h));
}

__device__ __forceinline__ void split_store4(float4 v,
                                             __half* __restrict__ pb,
                                             __half* __restrict__ pl,
                                             size_t i4) {
    __half hx, hy, hz, hw, lx, ly, lz, lw;
    split1(v.x, hx, lx); split1(v.y, hy, ly);
    split1(v.z, hz, lz); split1(v.w, hw, lw);
    ushort4 ub = make_ushort4(__half_as_ushort(hx), __half_as_ushort(hy),
                              __half_as_ushort(hz), __half_as_ushort(hw));
    ushort4 ul = make_ushort4(__half_as_ushort(lx), __half_as_ushort(ly),
                              __half_as_ushort(lz), __half_as_ushort(lw));
    reinterpret_cast<ushort4*>(pb)[i4] = ub;
    reinterpret_cast<ushort4*>(pl)[i4] = ul;
}

// =====================================================================
// Embedding lookup + fp16 split + zero a (for step 0)
// =====================================================================
__global__ __launch_bounds__(256) void k_embed(const int* __restrict__ x,
                                               const float* __restrict__ emb,
                                               int M) {
    int i = blockIdx.x * blockDim.x + threadIdx.x;
    if (i >= M * 64) return;
    int n = i >> 6, c = i & 63;
    int row = __ldg(x + n);
    float4 v = __ldg(reinterpret_cast<const float4*>(emb) + (size_t)row * 64 + c);
    reinterpret_cast<float4*>(g_h[0])[(size_t)n * 64 + c] = v;
    split_store4(v, g_hb, g_hl, (size_t)n * 64 + c);
    reinterpret_cast<float4*>(g_a)[i] = make_float4(0.f, 0.f, 0.f, 0.f);
}

// =====================================================================
// Pack all weights into fp16 (W1: t-weights + w_hh; W2: w_ih)
// =====================================================================
__global__ __launch_bounds__(256) void k_packW(const float* __restrict__ Wmsg,
                                               const float* __restrict__ w_hh,
                                               const float* __restrict__ w_ih) {
    int i = blockIdx.x * blockDim.x + threadIdx.x;
    if (i < N1 * DDIM) {
        int n = i >> 8, k = i & 255;
        float v;
        if (n < 768) {
            int e = n >> 8, c = n & 255;
            v = __ldg(Wmsg + (size_t)e * DDIM * DDIM + (size_t)k * DDIM + c);
        } else {
            v = __ldg(w_hh + (size_t)(n - 768) * DDIM + k);
        }
        g_W1h[i] = __float2half_rn(v);
    } else {
        int j = i - N1 * DDIM;
        if (j < N2 * DDIM) g_W2h[j] = __float2half_rn(__ldg(w_ih + j));
    }
}

// =====================================================================
// Convert a -> fp16 hi/lo
// =====================================================================
__global__ __launch_bounds__(256) void k_cvt_a(int M) {
    int i = blockIdx.x * blockDim.x + threadIdx.x;
    if (i >= M * 64) return;
    float4 v = reinterpret_cast<const float4*>(g_a)[i];
    split_store4(v, g_ab, g_al, i);
}

// =====================================================================
// mma.sync fp16x2 GEMM:  C[M, NLD] = (Ah+Al)[M,256] * Wh[Ncols,256]^T
// Extended K' = 512 = [Ah*Wh | Al*Wh], 8 chunks of k=64.
// CTA tile 128x128, 4 warps in 2(m) x 2(n), warp tile 64x64.
// 3-stage cp.async pipeline over 96KB dynamic smem, SW128 swizzle.
// =====================================================================
#define NCHUNK 8
#define BUFB   16384u          // bytes per stage buffer (128 rows x 128B)

__device__ __forceinline__ void ldmx4(uint32_t* r, uint32_t addr) {
    asm volatile(
        "ldmatrix.sync.aligned.m8n8.x4.shared.b16 {%0,%1,%2,%3}, [%4];"
        : "=r"(r[0]), "=r"(r[1]), "=r"(r[2]), "=r"(r[3]) : "r"(addr));
}

__device__ __forceinline__ void mma16816(float* c, const uint32_t* a,
                                         uint32_t b0, uint32_t b1) {
    asm volatile(
        "mma.sync.aligned.m16n8k16.row.col.f32.f16.f16.f32 "
        "{%0,%1,%2,%3}, {%4,%5,%6,%7}, {%8,%9}, {%0,%1,%2,%3};"
        : "+f"(c[0]), "+f"(c[1]), "+f"(c[2]), "+f"(c[3])
        : "r"(a[0]), "r"(a[1]), "r"(a[2]), "r"(a[3]), "r"(b0), "r"(b1));
}

__device__ __forceinline__ void cpa16(uint32_t dst, const void* src, int sz) {
    asm volatile("cp.async.cg.shared.global [%0], [%1], 16, %2;"
                 :: "r"(dst), "l"(src), "r"(sz));
}

// SW128-swizzled byte offset for (row, 16B-chunk cc in 0..7), 128B rows
__device__ __forceinline__ uint32_t swz(int row, int cc) {
    return (uint32_t)((row << 7) + ((cc ^ (row & 7)) << 4));
}

__global__ __launch_bounds__(128, 2)
void k_mma(const __half* __restrict__ Ah,
           const __half* __restrict__ Al,
           const __half* __restrict__ Bh,
           float* __restrict__ C, int M, int NLD) {
    extern __shared__ __align__(16) char dsm[];

    const int tid  = threadIdx.x;
    const int wid  = tid >> 5, lane = tid & 31;
    const int row0 = blockIdx.y * 128;
    const int col0 = blockIdx.x * 128;

    const uint32_t smA0 = smem_u32(dsm);            // A stages: [0, 48KB)
    const uint32_t smB0 = smA0 + 3 * BUFB;          // B stages: [48KB, 96KB)

    float acc[4][8][4];
#pragma unroll
    for (int i = 0; i < 4; i++)
#pragma unroll
        for (int j = 0; j < 8; j++)
#pragma unroll
            for (int q = 0; q < 4; q++) acc[i][j][q] = 0.f;

    const int lrow = lane & 15;
    const int lk8  = lane >> 4;              // 0/1: 16B half within a k16 slice
    const int warp_m = (wid & 1) << 6;       // 0,64
    const int warp_n = (wid >> 1) << 6;      // 0,64

    auto copy_chunk = [&](int c, int st) {
        int k0 = (c & 3) << 6;
        const __half* As = (c < 4) ? Ah : Al;
#pragma unroll
        for (int it = 0; it < 8; it++) {
            int idx = tid + it * 128;        // 0..1023
            int r = idx >> 3, cc = idx & 7;
            uint32_t so = swz(r, cc);
            {
                int gr = row0 + r;
                int sz = (gr < M) ? 16 : 0;
                cpa16(smA0 + st * BUFB + so,
                      As + (size_t)gr * DDIM + k0 + cc * 8, sz);
            }
            {
                int gr = col0 + r;           // always < Ncols
                cpa16(smB0 + st * BUFB + so,
                      Bh + (size_t)gr * DDIM + k0 + cc * 8, 16);
            }
        }
        asm volatile("cp.async.commit_group;");
    };

    copy_chunk(0, 0);
    copy_chunk(1, 1);

    int bi = 0;
    for (int c = 0; c < NCHUNK; c++) {
        if (c < NCHUNK - 1)
            asm volatile("cp.async.wait_group 1;");
        else
            asm volatile("cp.async.wait_group 0;");
        __syncthreads();                       // chunk c resident

        if (c + 2 < NCHUNK) copy_chunk(c + 2, (c + 2) % 3);

        uint32_t baseA = smA0 + bi * BUFB;
        uint32_t baseB = smB0 + bi * BUFB;

#pragma unroll
        for (int ks = 0; ks < 4; ks++) {       // four k16 slices within k64
            int cc = ks * 2 + lk8;
            uint32_t afr[4][4], bfr[4][4];
#pragma unroll
            for (int i = 0; i < 4; i++)
                ldmx4(afr[i], baseA + swz(warp_m + i * 16 + lrow, cc));
#pragma unroll
            for (int jj = 0; jj < 4; jj++)
                ldmx4(bfr[jj], baseB + swz(warp_n + jj * 16 + lrow, cc));
#pragma unroll
            for (int i = 0; i < 4; i++)
#pragma unroll
                for (int j = 0; j < 8; j++)
                    mma16816(acc[i][j], afr[i], bfr[j >> 1][j & 1],
                             bfr[j >> 1][(j & 1) + 2]);
        }
        bi = (bi + 1 == 3) ? 0 : bi + 1;
    }

    // epilogue
    const int erow = lane >> 2, ecol = (lane & 3) << 1;
#pragma unroll
    for (int i = 0; i < 4; i++) {
#pragma unroll
        for (int j = 0; j < 8; j++) {
            int gcol = col0 + warp_n + j * 8 + ecol;
            int r0 = row0 + warp_m + i * 16 + erow;
            if (r0 < M) {
                float2 v = make_float2(acc[i][j][0], acc[i][j][1]);
                *reinterpret_cast<float2*>(C + (size_t)r0 * NLD + gcol) = v;
            }
            if (r0 + 8 < M) {
                float2 v = make_float2(acc[i][j][2], acc[i][j][3]);
                *reinterpret_cast<float2*>(C + (size_t)(r0 + 8) * NLD + gcol) = v;
            }
        }
    }
}

// =====================================================================
// Edge scatter: a[dst] += t[etype][src] + b_msg[etype]
// =====================================================================
__global__ __launch_bounds__(256) void k_scatter(const int* __restrict__ src,
                                                 const int* __restrict__ dst,
                                                 const int* __restrict__ et,
                                                 const float* __restrict__ bmsg,
                                                 int E) {
    int warp = (blockIdx.x * blockDim.x + threadIdx.x) >> 5;
    int lane = threadIdx.x & 31;
    if (warp >= E) return;
    int s = __ldg(src + warp);
    int d = __ldg(dst + warp);
    int e = __ldg(et + warp);

    const float4* trow =
        reinterpret_cast<const float4*>(g_big + (size_t)s * N1 + (size_t)e * DDIM);
    const float4* brow =
        reinterpret_cast<const float4*>(bmsg + (size_t)e * DDIM);
    float* arow = g_a + (size_t)d * DDIM;

#pragma unroll
    for (int c = lane; c < 64; c += 32) {
        float4 v = __ldg(trow + c);
        float4 b = __ldg(brow + c);
        v.x += b.x; v.y += b.y; v.z += b.z; v.w += b.w;
        asm volatile("red.global.add.v4.f32 [%0], {%1,%2,%3,%4};"
                     :: "l"(arow + (c << 2)), "f"(v.x), "f"(v.y), "f"(v.z), "f"(v.w)
                     : "memory");
    }
}

// =====================================================================
// GRU elementwise; gh from g_big cols 768..1535, gi from g_gi.
// wsplit==0 on the final step; wzero==1 zeroes a for the next step.
// =====================================================================
__global__ __launch_bounds__(256) void k_gru(const float* __restrict__ b_ih,
                                             const float* __restrict__ b_hh,
                                             int M, int rbuf, int wbuf,
                                             int wsplit, int wzero) {
    int i = blockIdx.x * blockDim.x + threadIdx.x;
    if (i >= M * 64) return;
    int n = i >> 6, c = i & 63;

    const float4* gi4 = reinterpret_cast<const float4*>(g_gi) + (size_t)n * 192;
    const float4* gh4 = reinterpret_cast<const float4*>(g_big) + (size_t)n * 384 + 192;
    const float4* bi4 = reinterpret_cast<const float4*>(b_ih);
    const float4* bh4 = reinterpret_cast<const float4*>(b_hh);

    float4 ir  = gi4[c],       hr = gh4[c];
    float4 iz  = gi4[64 + c],  hz = gh4[64 + c];
    float4 in_ = gi4[128 + c], hn = gh4[128 + c];
    float4 bir = __ldg(bi4 + c), biz = __ldg(bi4 + 64 + c), bin_ = __ldg(bi4 + 128 + c);
    float4 bhr = __ldg(bh4 + c), bhz = __ldg(bh4 + 64 + c), bhn  = __ldg(bh4 + 128 + c);
    float4 ho  = reinterpret_cast<const float4*>(g_h[rbuf])[(size_t)n * 64 + c];

    float4 res;
#define GRU_COMP(f)                                                        \
    {                                                                      \
        float r  = sigf(ir.f + bir.f + hr.f + bhr.f);                      \
        float z  = sigf(iz.f + biz.f + hz.f + bhz.f);                      \
        float nn = tanhf(in_.f + bin_.f + r * (hn.f + bhn.f));             \
        res.f = (1.f - z) * nn + z * ho.f;                                 \
    }
    GRU_COMP(x) GRU_COMP(y) GRU_COMP(z) GRU_COMP(w)
#undef GRU_COMP

    reinterpret_cast<float4*>(g_h[wbuf])[(size_t)n * 64 + c] = res;
    if (wsplit) split_store4(res, g_hb, g_hl, (size_t)n * 64 + c);
    if (wzero)
        reinterpret_cast<float4*>(g_a)[i] = make_float4(0.f, 0.f, 0.f, 0.f);
}

// =====================================================================
// Gate score (one warp per node)
// =====================================================================
__global__ __launch_bounds__(256) void k_gate(const float* __restrict__ gw,
                                              const float* __restrict__ gb,
                                              int M, int buf) {
    int warp = (blockIdx.x * blockDim.x + threadIdx.x) >> 5;
    int lane = threadIdx.x & 31;
    if (warp >= M) return;
    const float4* hr =
        reinterpret_cast<const float4*>(g_h[buf] + (size_t)warp * DDIM);
    const float4* w4 = reinterpret_cast<const float4*>(gw);
    float s = 0.f;
#pragma unroll
    for (int c = lane; c < 64; c += 32) {
        float4 a = hr[c], b = __ldg(w4 + c);
        s += a.x * b.x + a.y * b.y + a.z * b.z + a.w * b.w;
    }
#pragma unroll
    for (int o = 16; o; o >>= 1) s += __shfl_xor_sync(0xffffffffu, s, o);
    if (lane == 0) g_gate[warp] = s + __ldg(gb);
}

// =====================================================================
// Pooling: per-graph softmax over gate, weighted sum of h
// =====================================================================
__device__ __forceinline__ int lower_bound_dev(const int* __restrict__ a,
                                               int n, int v) {
    int lo = 0, hi = n;
    while (lo < hi) {
        int mid = (lo + hi) >> 1;
        if (a[mid] < v) lo = mid + 1; else hi = mid;
    }
    return lo;
}

__global__ __launch_bounds__(256) void k_pool(const int* __restrict__ seg,
                                              float* __restrict__ out,
                                              int M, int buf) {
    int g = blockIdx.x;
    int lo = lower_bound_dev(seg, M, g);
    int hi = lower_bound_dev(seg, M, g + 1);
    const float* h = g_h[buf];

    __shared__ float red[256];
    __shared__ float ew[256];
    int tid = threadIdx.x;

    float m = -1e30f;
    for (int i = lo + tid; i < hi; i += 256) m = fmaxf(m, g_gate[i]);
    red[tid] = m;
    __syncthreads();
    for (int s = 128; s > 0; s >>= 1) {
        if (tid < s) red[tid] = fmaxf(red[tid], red[tid + s]);
        __syncthreads();
    }
    m = red[0];
    __syncthreads();

    float sum = 0.f;
    for (int i = lo + tid; i < hi; i += 256) sum += __expf(g_gate[i] - m);
    red[tid] = sum;
    __syncthreads();
    for (int s = 128; s > 0; s >>= 1) {
        if (tid < s) red[tid] += red[tid + s];
        __syncthreads();
    }
    float inv = (hi > lo) ? 1.f / red[0] : 0.f;
    __syncthreads();

    float acc = 0.f;
    for (int base = lo; base < hi; base += 256) {
        int cnt = min(256, hi - base);
        if (tid < cnt) ew[tid] = __expf(g_gate[base + tid] - m) * inv;
        __syncthreads();
        for (int j = 0; j < cnt; j++)
            acc += ew[j] * h[(size_t)(base + j) * DDIM + tid];
        __syncthreads();
    }
    out[(size_t)g * DDIM + tid] = acc;
}

// =====================================================================
// launcher — single stream, minimal launches.
// Global launch order: embed(0), packW(1), mma(2), scatter(3 = profiled),
// then cvt, mma, gru per step.
// =====================================================================
#define DSMEM_BYTES 98304

extern "C" void kernel_launch(void* const* d_in, const int* in_sizes, int n_in,
                              void* d_out, int out_size) {
    const int* x   = (const int*)d_in[0];
    const int* src = (const int*)d_in[1];
    const int* dst = (const int*)d_in[2];
    const int* et  = (const int*)d_in[3];
    const int* seg = (const int*)d_in[4];

    int off = (in_sizes[5] == 1) ? 1 : 0;
    const float* emb  = (const float*)d_in[5 + off];
    const float* Wmsg = (const float*)d_in[6 + off];
    const float* bmsg = (const float*)d_in[7 + off];
    const float* w_ih = (const float*)d_in[8 + off];
    const float* w_hh = (const float*)d_in[9 + off];
    const float* b_ih = (const float*)d_in[10 + off];
    const float* b_hh = (const float*)d_in[11 + off];
    const float* gw   = (const float*)d_in[12 + off];
    const float* gb   = (const float*)d_in[13 + off];

    int M = in_sizes[0];
    int E = in_sizes[1];
    int G = out_size / DDIM;
    float* out = (float*)d_out;

    int eltBlocks = (M * 64 + 255) / 256;
    int mb = (M + 127) / 128;

    __half *hb, *hl, *ab, *al, *w1h, *w2h;
    float *big, *gi;
    cudaGetSymbolAddress((void**)&hb,  g_hb);
    cudaGetSymbolAddress((void**)&hl,  g_hl);
    cudaGetSymbolAddress((void**)&ab,  g_ab);
    cudaGetSymbolAddress((void**)&al,  g_al);
    cudaGetSymbolAddress((void**)&w1h, g_W1h);
    cudaGetSymbolAddress((void**)&w2h, g_W2h);
    cudaGetSymbolAddress((void**)&big, g_big);
    cudaGetSymbolAddress((void**)&gi,  g_gi);

    // opt-in to 96KB dynamic smem (attribute set, not an allocation)
    cudaFuncSetAttribute(k_mma, cudaFuncAttributeMaxDynamicSharedMemorySize,
                         DSMEM_BYTES);

    k_embed<<<eltBlocks, 256>>>(x, emb, M);
    k_packW<<<((N1 + N2) * DDIM + 255) / 256, 256>>>(Wmsg, w_hh, w_ih);

    for (int s = 0; s < NSTEPS; s++) {
        int rb = s & 1, wb = rb ^ 1;
        // t + gh in one GEMM launch (cols 0..1535 of g_big)
        k_mma<<<dim3(N1 / 128, mb), 128, DSMEM_BYTES>>>(hb, hl, w1h, big, M, N1);
        k_scatter<<<(E * 32 + 255) / 256, 256>>>(src, dst, et, bmsg, E);
        k_cvt_a<<<eltBlocks, 256>>>(M);
        k_mma<<<dim3(N2 / 128, mb), 128, DSMEM_BYTES>>>(ab, al, w2h, gi, M, N2);
        k_gru<<<eltBlocks, 256>>>(b_ih, b_hh, M, rb, wb,
                                  (s + 1 < NSTEPS) ? 1 : 0,
                                  (s + 1 < NSTEPS) ? 1 : 0);
    }

    int fb = NSTEPS & 1;
    k_gate<<<(M * 32 + 255) / 256, 256>>>(gw, gb, M, fb);
    k_pool<<<G, 256>>>(seg, out, M, fb);
}

// round 17
// speedup vs baseline: 1.0214x; 1.0214x over previous
#include <cuda_runtime.h>
#include <cuda_fp16.h>
#include <cstdint>

// ---------------- problem constants ----------------
#define MAXN   50000
#define DDIM   256
#define NSTEPS 5
#define NT     768             // t cols (3*256), stored fp16
#define N2     768             // gh / gi cols (fp32)

// ---------------- device-global scratch ----------------
__device__ float g_h[2][(size_t)MAXN * DDIM];        // ping-pong node state (fp32)
__device__ __half g_t16[(size_t)MAXN * NT];          // t fp16 (77MB, L2-resident)
__device__ float g_gh[(size_t)MAXN * N2];            // h @ w_hh^T
__device__ float g_gi[(size_t)MAXN * N2];            // a @ w_ih^T
__device__ float g_a[(size_t)MAXN * DDIM];           // aggregated messages
__device__ float g_gate[MAXN];

__device__ __half g_hb[(size_t)MAXN * DDIM];         // h split hi (fp16)
__device__ __half g_hl[(size_t)MAXN * DDIM];         // h split lo
__device__ __half g_ab[(size_t)MAXN * DDIM];         // a split hi
__device__ __half g_al[(size_t)MAXN * DDIM];         // a split lo
__device__ __half g_W1h[(NT + N2) * DDIM];           // [t-weights | w_hh] fp16
__device__ __half g_W2h[N2 * DDIM];                  // w_ih fp16

// ---------------- small helpers ----------------
__device__ __forceinline__ float sigf(float x) { return 1.f / (1.f + __expf(-x)); }

__device__ __forceinline__ uint32_t smem_u32(const void* p) {
    uint32_t a;
    asm("{ .reg .u64 t; cvta.to.shared.u64 t, %1; cvt.u32.u64 %0, t; }"
        : "=r"(a) : "l"(p));
    return a;
}

__device__ __forceinline__ void split1(float v, __half& h, __half& l) {
    h = __float2half_rn(v);
    l = __float2half_rn(v - __half2float(h));
}

__device__ __forceinline__ void split_store4(float4 v,
                                             __half* __restrict__ pb,
                                             __half* __restrict__ pl,
                                             size_t i4) {
    __half hx, hy, hz, hw, lx, ly, lz, lw;
    split1(v.x, hx, lx); split1(v.y, hy, ly);
    split1(v.z, hz, lz); split1(v.w, hw, lw);
    ushort4 ub = make_ushort4(__half_as_ushort(hx), __half_as_ushort(hy),
                              __half_as_ushort(hz), __half_as_ushort(hw));
    ushort4 ul = make_ushort4(__half_as_ushort(lx), __half_as_ushort(ly),
                              __half_as_ushort(lz), __half_as_ushort(lw));
    reinterpret_cast<ushort4*>(pb)[i4] = ub;
    reinterpret_cast<ushort4*>(pl)[i4] = ul;
}

// =====================================================================
// Embedding lookup + fp16 split + zero a (for step 0)
// =====================================================================
__global__ __launch_bounds__(256) void k_embed(const int* __restrict__ x,
                                               const float* __restrict__ emb,
                                               int M) {
    int i = blockIdx.x * blockDim.x + threadIdx.x;
    if (i >= M * 64) return;
    int n = i >> 6, c = i & 63;
    int row = __ldg(x + n);
    float4 v = __ldg(reinterpret_cast<const float4*>(emb) + (size_t)row * 64 + c);
    reinterpret_cast<float4*>(g_h[0])[(size_t)n * 64 + c] = v;
    split_store4(v, g_hb, g_hl, (size_t)n * 64 + c);
    reinterpret_cast<float4*>(g_a)[i] = make_float4(0.f, 0.f, 0.f, 0.f);
}

// =====================================================================
// Pack all weights into fp16
// =====================================================================
__global__ __launch_bounds__(256) void k_packW(const float* __restrict__ Wmsg,
                                               const float* __restrict__ w_hh,
                                               const float* __restrict__ w_ih) {
    int i = blockIdx.x * blockDim.x + threadIdx.x;
    if (i < (NT + N2) * DDIM) {
        int n = i >> 8, k = i & 255;
        float v;
        if (n < NT) {
            int e = n >> 8, c = n & 255;
            v = __ldg(Wmsg + (size_t)e * DDIM * DDIM + (size_t)k * DDIM + c);
        } else {
            v = __ldg(w_hh + (size_t)(n - NT) * DDIM + k);
        }
        g_W1h[i] = __float2half_rn(v);
    } else {
        int j = i - (NT + N2) * DDIM;
        if (j < N2 * DDIM) g_W2h[j] = __float2half_rn(__ldg(w_ih + j));
    }
}

// =====================================================================
// Convert a -> fp16 hi/lo
// =====================================================================
__global__ __launch_bounds__(256) void k_cvt_a(int M) {
    int i = blockIdx.x * blockDim.x + threadIdx.x;
    if (i >= M * 64) return;
    float4 v = reinterpret_cast<const float4*>(g_a)[i];
    split_store4(v, g_ab, g_al, i);
}

// =====================================================================
// mma.sync fp16x2 GEMM:  C[M, NLD] = (Ah+Al)[M,256] * Wh[Ncols,256]^T
// K' = 512 = [Ah*Wh | Al*Wh], 8 chunks of k=64.
// CTA tile 128x128, 4 warps 2x2, warp tile 64x64, 3-stage cp.async,
// 96KB dynamic smem, SW128 swizzle. OUT16 selects fp16/fp32 store.
// =====================================================================
#define NCHUNK 8
#define BUFB   16384u

__device__ __forceinline__ void ldmx4(uint32_t* r, uint32_t addr) {
    asm volatile(
        "ldmatrix.sync.aligned.m8n8.x4.shared.b16 {%0,%1,%2,%3}, [%4];"
        : "=r"(r[0]), "=r"(r[1]), "=r"(r[2]), "=r"(r[3]) : "r"(addr));
}

__device__ __forceinline__ void mma16816(float* c, const uint32_t* a,
                                         uint32_t b0, uint32_t b1) {
    asm volatile(
        "mma.sync.aligned.m16n8k16.row.col.f32.f16.f16.f32 "
        "{%0,%1,%2,%3}, {%4,%5,%6,%7}, {%8,%9}, {%0,%1,%2,%3};"
        : "+f"(c[0]), "+f"(c[1]), "+f"(c[2]), "+f"(c[3])
        : "r"(a[0]), "r"(a[1]), "r"(a[2]), "r"(a[3]), "r"(b0), "r"(b1));
}

__device__ __forceinline__ void cpa16(uint32_t dst, const void* src, int sz) {
    asm volatile("cp.async.cg.shared.global [%0], [%1], 16, %2;"
                 :: "r"(dst), "l"(src), "r"(sz));
}

__device__ __forceinline__ uint32_t swz(int row, int cc) {
    return (uint32_t)((row << 7) + ((cc ^ (row & 7)) << 4));
}

template <bool OUT16>
__global__ __launch_bounds__(128, 2)
void k_mma(const __half* __restrict__ Ah,
           const __half* __restrict__ Al,
           const __half* __restrict__ Bh,
           void* __restrict__ Cv, int M, int NLD) {
    extern __shared__ __align__(16) char dsm[];

    const int tid  = threadIdx.x;
    const int wid  = tid >> 5, lane = tid & 31;
    const int row0 = blockIdx.y * 128;
    const int col0 = blockIdx.x * 128;

    const uint32_t smA0 = smem_u32(dsm);
    const uint32_t smB0 = smA0 + 3 * BUFB;

    float acc[4][8][4];
#pragma unroll
    for (int i = 0; i < 4; i++)
#pragma unroll
        for (int j = 0; j < 8; j++)
#pragma unroll
            for (int q = 0; q < 4; q++) acc[i][j][q] = 0.f;

    const int lrow = lane & 15;
    const int lk8  = lane >> 4;
    const int warp_m = (wid & 1) << 6;
    const int warp_n = (wid >> 1) << 6;

    auto copy_chunk = [&](int c, int st) {
        int k0 = (c & 3) << 6;
        const __half* As = (c < 4) ? Ah : Al;
#pragma unroll
        for (int it = 0; it < 8; it++) {
            int idx = tid + it * 128;
            int r = idx >> 3, cc = idx & 7;
            uint32_t so = swz(r, cc);
            {
                int gr = row0 + r;
                int sz = (gr < M) ? 16 : 0;
                cpa16(smA0 + st * BUFB + so,
                      As + (size_t)gr * DDIM + k0 + cc * 8, sz);
            }
            {
                int gr = col0 + r;
                cpa16(smB0 + st * BUFB + so,
                      Bh + (size_t)gr * DDIM + k0 + cc * 8, 16);
            }
        }
        asm volatile("cp.async.commit_group;");
    };

    copy_chunk(0, 0);
    copy_chunk(1, 1);

    int bi = 0;
    for (int c = 0; c < NCHUNK; c++) {
        if (c < NCHUNK - 1)
            asm volatile("cp.async.wait_group 1;");
        else
            asm volatile("cp.async.wait_group 0;");
        __syncthreads();

        if (c + 2 < NCHUNK) copy_chunk(c + 2, (c + 2) % 3);

        uint32_t baseA = smA0 + bi * BUFB;
        uint32_t baseB = smB0 + bi * BUFB;

#pragma unroll
        for (int ks = 0; ks < 4; ks++) {
            int cc = ks * 2 + lk8;
            uint32_t afr[4][4], bfr[4][4];
#pragma unroll
            for (int i = 0; i < 4; i++)
                ldmx4(afr[i], baseA + swz(warp_m + i * 16 + lrow, cc));
#pragma unroll
            for (int jj = 0; jj < 4; jj++)
                ldmx4(bfr[jj], baseB + swz(warp_n + jj * 16 + lrow, cc));
#pragma unroll
            for (int i = 0; i < 4; i++)
#pragma unroll
                for (int j = 0; j < 8; j++)
                    mma16816(acc[i][j], afr[i], bfr[j >> 1][j & 1],
                             bfr[j >> 1][(j & 1) + 2]);
        }
        bi = (bi + 1 == 3) ? 0 : bi + 1;
    }

    const int erow = lane >> 2, ecol = (lane & 3) << 1;
#pragma unroll
    for (int i = 0; i < 4; i++) {
#pragma unroll
        for (int j = 0; j < 8; j++) {
            int gcol = col0 + warp_n + j * 8 + ecol;
            int r0 = row0 + warp_m + i * 16 + erow;
            if (OUT16) {
                __half* C = reinterpret_cast<__half*>(Cv);
                if (r0 < M)
                    *reinterpret_cast<__half2*>(C + (size_t)r0 * NLD + gcol) =
                        __floats2half2_rn(acc[i][j][0], acc[i][j][1]);
                if (r0 + 8 < M)
                    *reinterpret_cast<__half2*>(C + (size_t)(r0 + 8) * NLD + gcol) =
                        __floats2half2_rn(acc[i][j][2], acc[i][j][3]);
            } else {
                float* C = reinterpret_cast<float*>(Cv);
                if (r0 < M) {
                    float2 v = make_float2(acc[i][j][0], acc[i][j][1]);
                    *reinterpret_cast<float2*>(C + (size_t)r0 * NLD + gcol) = v;
                }
                if (r0 + 8 < M) {
                    float2 v = make_float2(acc[i][j][2], acc[i][j][3]);
                    *reinterpret_cast<float2*>(C + (size_t)(r0 + 8) * NLD + gcol) = v;
                }
            }
        }
    }
}

// =====================================================================
// Edge scatter: a[dst] += float(t16[etype][src]) + b_msg[etype]
// SAME access pattern as the measured-good fp32 version:
// lane handles float4 positions c=lane and c=lane+32; red.v4 contiguous.
// Only the gather load shrinks to uint2 (8B of fp16).
// =====================================================================
__global__ __launch_bounds__(256) void k_scatter(const int* __restrict__ src,
                                                 const int* __restrict__ dst,
                                                 const int* __restrict__ et,
                                                 const float* __restrict__ bmsg,
                                                 int E) {
    int warp = (blockIdx.x * blockDim.x + threadIdx.x) >> 5;
    int lane = threadIdx.x & 31;
    if (warp >= E) return;
    int s = __ldg(src + warp);
    int d = __ldg(dst + warp);
    int e = __ldg(et + warp);

    const __half2* trow = reinterpret_cast<const __half2*>(
        g_t16 + (size_t)s * NT + (size_t)e * DDIM);
    const float4* brow =
        reinterpret_cast<const float4*>(bmsg + (size_t)e * DDIM);
    float* arow = g_a + (size_t)d * DDIM;

#pragma unroll
    for (int c = lane; c < 64; c += 32) {
        // 8B load = 2 half2 = one float4's worth of values
        uint2 raw = __ldg(reinterpret_cast<const uint2*>(trow + c * 2));
        __half2 h0 = *reinterpret_cast<__half2*>(&raw.x);
        __half2 h1 = *reinterpret_cast<__half2*>(&raw.y);
        float2 p0 = __half22float2(h0);
        float2 p1 = __half22float2(h1);
        float4 b = __ldg(brow + c);
        asm volatile("red.global.add.v4.f32 [%0], {%1,%2,%3,%4};"
                     :: "l"(arow + (c << 2)),
                        "f"(p0.x + b.x), "f"(p0.y + b.y),
                        "f"(p1.x + b.z), "f"(p1.y + b.w) : "memory");
    }
}

// =====================================================================
// GRU elementwise; gh from g_gh, gi from g_gi.
// wsplit==0 on final step; wzero==1 zeroes a for next step.
// =====================================================================
__global__ __launch_bounds__(256) void k_gru(const float* __restrict__ b_ih,
                                             const float* __restrict__ b_hh,
                                             int M, int rbuf, int wbuf,
                                             int wsplit, int wzero) {
    int i = blockIdx.x * blockDim.x + threadIdx.x;
    if (i >= M * 64) return;
    int n = i >> 6, c = i & 63;

    const float4* gi4 = reinterpret_cast<const float4*>(g_gi) + (size_t)n * 192;
    const float4* gh4 = reinterpret_cast<const float4*>(g_gh) + (size_t)n * 192;
    const float4* bi4 = reinterpret_cast<const float4*>(b_ih);
    const float4* bh4 = reinterpret_cast<const float4*>(b_hh);

    float4 ir  = gi4[c],       hr = gh4[c];
    float4 iz  = gi4[64 + c],  hz = gh4[64 + c];
    float4 in_ = gi4[128 + c], hn = gh4[128 + c];
    float4 bir = __ldg(bi4 + c), biz = __ldg(bi4 + 64 + c), bin_ = __ldg(bi4 + 128 + c);
    float4 bhr = __ldg(bh4 + c), bhz = __ldg(bh4 + 64 + c), bhn  = __ldg(bh4 + 128 + c);
    float4 ho  = reinterpret_cast<const float4*>(g_h[rbuf])[(size_t)n * 64 + c];

    float4 res;
#define GRU_COMP(f)                                                        \
    {                                                                      \
        float r  = sigf(ir.f + bir.f + hr.f + bhr.f);                      \
        float z  = sigf(iz.f + biz.f + hz.f + bhz.f);                      \
        float nn = tanhf(in_.f + bin_.f + r * (hn.f + bhn.f));             \
        res.f = (1.f - z) * nn + z * ho.f;                                 \
    }
    GRU_COMP(x) GRU_COMP(y) GRU_COMP(z) GRU_COMP(w)
#undef GRU_COMP

    reinterpret_cast<float4*>(g_h[wbuf])[(size_t)n * 64 + c] = res;
    if (wsplit) split_store4(res, g_hb, g_hl, (size_t)n * 64 + c);
    if (wzero)
        reinterpret_cast<float4*>(g_a)[i] = make_float4(0.f, 0.f, 0.f, 0.f);
}

// =====================================================================
// Gate score (one warp per node)
// =====================================================================
__global__ __launch_bounds__(256) void k_gate(const float* __restrict__ gw,
                                              const float* __restrict__ gb,
                                              int M, int buf) {
    int warp = (blockIdx.x * blockDim.x + threadIdx.x) >> 5;
    int lane = threadIdx.x & 31;
    if (warp >= M) return;
    const float4* hr =
        reinterpret_cast<const float4*>(g_h[buf] + (size_t)warp * DDIM);
    const float4* w4 = reinterpret_cast<const float4*>(gw);
    float s = 0.f;
#pragma unroll
    for (int c = lane; c < 64; c += 32) {
        float4 a = hr[c], b = __ldg(w4 + c);
        s += a.x * b.x + a.y * b.y + a.z * b.z + a.w * b.w;
    }
#pragma unroll
    for (int o = 16; o; o >>= 1) s += __shfl_xor_sync(0xffffffffu, s, o);
    if (lane == 0) g_gate[warp] = s + __ldg(gb);
}

// =====================================================================
// Pooling
// =====================================================================
__device__ __forceinline__ int lower_bound_dev(const int* __restrict__ a,
                                               int n, int v) {
    int lo = 0, hi = n;
    while (lo < hi) {
        int mid = (lo + hi) >> 1;
        if (a[mid] < v) lo = mid + 1; else hi = mid;
    }
    return lo;
}

__global__ __launch_bounds__(256) void k_pool(const int* __restrict__ seg,
                                              float* __restrict__ out,
                                              int M, int buf) {
    int g = blockIdx.x;
    int lo = lower_bound_dev(seg, M, g);
    int hi = lower_bound_dev(seg, M, g + 1);
    const float* h = g_h[buf];

    __shared__ float red[256];
    __shared__ float ew[256];
    int tid = threadIdx.x;

    float m = -1e30f;
    for (int i = lo + tid; i < hi; i += 256) m = fmaxf(m, g_gate[i]);
    red[tid] = m;
    __syncthreads();
    for (int s = 128; s > 0; s >>= 1) {
        if (tid < s) red[tid] = fmaxf(red[tid], red[tid + s]);
        __syncthreads();
    }
    m = red[0];
    __syncthreads();

    float sum = 0.f;
    for (int i = lo + tid; i < hi; i += 256) sum += __expf(g_gate[i] - m);
    red[tid] = sum;
    __syncthreads();
    for (int s = 128; s > 0; s >>= 1) {
        if (tid < s) red[tid] += red[tid + s];
        __syncthreads();
    }
    float inv = (hi > lo) ? 1.f / red[0] : 0.f;
    __syncthreads();

    float acc = 0.f;
    for (int base = lo; base < hi; base += 256) {
        int cnt = min(256, hi - base);
        if (tid < cnt) ew[tid] = __expf(g_gate[base + tid] - m) * inv;
        __syncthreads();
        for (int j = 0; j < cnt; j++)
            acc += ew[j] * h[(size_t)(base + j) * DDIM + tid];
        __syncthreads();
    }
    out[(size_t)g * DDIM + tid] = acc;
}

// =====================================================================
// launcher — single stream.
// Launch order: embed(0), packW(1), mma_t(2), scatter(3 = profiled), ...
// =====================================================================
#define DSMEM_BYTES 98304

extern "C" void kernel_launch(void* const* d_in, const int* in_sizes, int n_in,
                              void* d_out, int out_size) {
    const int* x   = (const int*)d_in[0];
    const int* src = (const int*)d_in[1];
    const int* dst = (const int*)d_in[2];
    const int* et  = (const int*)d_in[3];
    const int* seg = (const int*)d_in[4];

    int off = (in_sizes[5] == 1) ? 1 : 0;
    const float* emb  = (const float*)d_in[5 + off];
    const float* Wmsg = (const float*)d_in[6 + off];
    const float* bmsg = (const float*)d_in[7 + off];
    const float* w_ih = (const float*)d_in[8 + off];
    const float* w_hh = (const float*)d_in[9 + off];
    const float* b_ih = (const float*)d_in[10 + off];
    const float* b_hh = (const float*)d_in[11 + off];
    const float* gw   = (const float*)d_in[12 + off];
    const float* gb   = (const float*)d_in[13 + off];

    int M = in_sizes[0];
    int E = in_sizes[1];
    int G = out_size / DDIM;
    float* out = (float*)d_out;

    int eltBlocks = (M * 64 + 255) / 256;
    int mb = (M + 127) / 128;

    __half *hb, *hl, *ab, *al, *w1h, *w2h, *t16;
    float *gh, *gi;
    cudaGetSymbolAddress((void**)&hb,  g_hb);
    cudaGetSymbolAddress((void**)&hl,  g_hl);
    cudaGetSymbolAddress((void**)&ab,  g_ab);
    cudaGetSymbolAddress((void**)&al,  g_al);
    cudaGetSymbolAddress((void**)&w1h, g_W1h);
    cudaGetSymbolAddress((void**)&w2h, g_W2h);
    cudaGetSymbolAddress((void**)&t16, g_t16);
    cudaGetSymbolAddress((void**)&gh,  g_gh);
    cudaGetSymbolAddress((void**)&gi,  g_gi);

    cudaFuncSetAttribute(k_mma<false>,
                         cudaFuncAttributeMaxDynamicSharedMemorySize, DSMEM_BYTES);
    cudaFuncSetAttribute(k_mma<true>,
                         cudaFuncAttributeMaxDynamicSharedMemorySize, DSMEM_BYTES);

    k_embed<<<eltBlocks, 256>>>(x, emb, M);
    k_packW<<<(((NT + N2) + N2) * DDIM + 255) / 256, 256>>>(Wmsg, w_hh, w_ih);

    for (int s = 0; s < NSTEPS; s++) {
        int rb = s & 1, wb = rb ^ 1;
        k_mma<true><<<dim3(NT / 128, mb), 128, DSMEM_BYTES>>>(
            hb, hl, w1h, t16, M, NT);
        k_scatter<<<(E * 32 + 255) / 256, 256>>>(src, dst, et, bmsg, E);
        k_mma<false><<<dim3(N2 / 128, mb), 128, DSMEM_BYTES>>>(
            hb, hl, w1h + (size_t)NT * DDIM, gh, M, N2);
        k_cvt_a<<<eltBlocks, 256>>>(M);
        k_mma<false><<<dim3(N2 / 128, mb), 128, DSMEM_BYTES>>>(
            ab, al, w2h, gi, M, N2);
        k_gru<<<eltBlocks, 256>>>(b_ih, b_hh, M, rb, wb,
                                  (s + 1 < NSTEPS) ? 1 : 0,
                                  (s + 1 < NSTEPS) ? 1 : 0);
    }

    int fb = NSTEPS & 1;
    k_gate<<<(M * 32 + 255) / 256, 256>>>(gw, gb, M, fb);
    k_pool<<<G, 256>>>(seg, out, M, fb);
}